// round 1
// baseline (speedup 1.0000x reference)
#include <cuda_runtime.h>
#include <math.h>

// Problem constants
#define Bz 2
#define Sq 1024
#define Dm 1024
#define Hh 16
#define Ll 6
#define Vv 50257
#define HDm 64
#define MROWS (Bz * Sq)   // 2048
#define FFd (4 * Dm)      // 4096

// Scratch (device globals: no allocation allowed in kernel_launch)
__device__ float g_x[MROWS * Dm];     // residual stream
__device__ float g_h[MROWS * Dm];     // layernorm output / generic temp
__device__ float g_q[MROWS * Dm];
__device__ float g_k[MROWS * Dm];
__device__ float g_v[MROWS * Dm];
__device__ float g_att[MROWS * Dm];
__device__ float g_ff[MROWS * FFd];

// ---------------------------------------------------------------------------
// Embedding: x[b,s,:] = tok_emb[tokens[b,s],:] + pos_emb[s,:]
// ---------------------------------------------------------------------------
__global__ void embed_kernel(const int* __restrict__ tokens,
                             const float* __restrict__ tok_emb,
                             const float* __restrict__ pos_emb) {
    int idx = blockIdx.x * blockDim.x + threadIdx.x;   // over MROWS*Dm/4
    if (idx >= MROWS * Dm / 4) return;
    int row = idx / (Dm / 4);
    int c4  = idx % (Dm / 4);
    int s   = row % Sq;
    int tok = tokens[row];
    float4 te = reinterpret_cast<const float4*>(tok_emb + (size_t)tok * Dm)[c4];
    float4 pe = reinterpret_cast<const float4*>(pos_emb + (size_t)s * Dm)[c4];
    te.x += pe.x; te.y += pe.y; te.z += pe.z; te.w += pe.w;
    reinterpret_cast<float4*>(g_x)[idx] = te;
}

// ---------------------------------------------------------------------------
// LayerNorm: one block per row (2048 rows), 256 threads, D=1024
// ---------------------------------------------------------------------------
__global__ __launch_bounds__(256) void ln_kernel(const float* __restrict__ x,
                                                 const float* __restrict__ gw,
                                                 const float* __restrict__ bw,
                                                 float* __restrict__ out) {
    int row = blockIdx.x;
    int tid = threadIdx.x;
    const float* xr = x + (size_t)row * Dm;

    float v[4];
    float s = 0.f, s2 = 0.f;
#pragma unroll
    for (int i = 0; i < 4; i++) {
        v[i] = xr[tid + i * 256];
        s += v[i];
        s2 += v[i] * v[i];
    }
#pragma unroll
    for (int o = 16; o > 0; o >>= 1) {
        s  += __shfl_xor_sync(0xffffffffu, s,  o);
        s2 += __shfl_xor_sync(0xffffffffu, s2, o);
    }
    __shared__ float ws[8], ws2[8];
    int w = tid >> 5, l = tid & 31;
    if (l == 0) { ws[w] = s; ws2[w] = s2; }
    __syncthreads();
    s = 0.f; s2 = 0.f;
#pragma unroll
    for (int i = 0; i < 8; i++) { s += ws[i]; s2 += ws2[i]; }
    float mean = s * (1.0f / Dm);
    float var  = s2 * (1.0f / Dm) - mean * mean;
    float rstd = rsqrtf(var + 1e-5f);

    float* orow = out + (size_t)row * Dm;
#pragma unroll
    for (int i = 0; i < 4; i++) {
        int col = tid + i * 256;
        orow[col] = (v[i] - mean) * rstd * gw[col] + bw[col];
    }
}

// ---------------------------------------------------------------------------
// GEMM: C[M,N] = A[M,K] @ B  (B is [K,N], or [N,K] if TB)
// 128x128 tile, BK=8, 256 threads, 8x8 per thread.
// Epilogue OP: 0 none, 1 +res, 2 gelu(acc+bias), 3 res+acc+bias
// ---------------------------------------------------------------------------
template <int OP, bool TB>
__device__ __forceinline__ void gemm_body(const float* __restrict__ A,
                                          const float* __restrict__ Bm,
                                          const float* __restrict__ bias,
                                          const float* __restrict__ res,
                                          float* __restrict__ C,
                                          int M, int N, int K, int m0, int n0) {
    __shared__ float As[8][128];
    __shared__ float Bs[8][128];

    int tid = threadIdx.x;
    int tx = tid & 15, ty = tid >> 4;

    float acc[8][8];
#pragma unroll
    for (int i = 0; i < 8; i++)
#pragma unroll
        for (int j = 0; j < 8; j++) acc[i][j] = 0.f;

    int ar = tid >> 1;          // 0..127
    int ac = (tid & 1) * 4;     // 0 or 4
    int br = tid >> 5;          // 0..7
    int bc = (tid & 31) * 4;    // 0..124

    for (int k0 = 0; k0 < K; k0 += 8) {
        // A tile (M,K row-major): 128 rows x 8 k, transpose into As[k][m]
        float4 av = *reinterpret_cast<const float4*>(A + (size_t)(m0 + ar) * K + k0 + ac);
        As[ac + 0][ar] = av.x;
        As[ac + 1][ar] = av.y;
        As[ac + 2][ar] = av.z;
        As[ac + 3][ar] = av.w;
        if (!TB) {
            float4 bv = *reinterpret_cast<const float4*>(Bm + (size_t)(k0 + br) * N + n0 + bc);
            *reinterpret_cast<float4*>(&Bs[br][bc]) = bv;
        } else {
            int n = n0 + ar;
            float4 bv = make_float4(0.f, 0.f, 0.f, 0.f);
            if (n < N)
                bv = *reinterpret_cast<const float4*>(Bm + (size_t)n * K + k0 + ac);
            Bs[ac + 0][ar] = bv.x;
            Bs[ac + 1][ar] = bv.y;
            Bs[ac + 2][ar] = bv.z;
            Bs[ac + 3][ar] = bv.w;
        }
        __syncthreads();
#pragma unroll
        for (int kk = 0; kk < 8; kk++) {
            float a[8], b[8];
#pragma unroll
            for (int i = 0; i < 8; i++) a[i] = As[kk][ty * 8 + i];
#pragma unroll
            for (int j = 0; j < 8; j++) b[j] = Bs[kk][tx * 8 + j];
#pragma unroll
            for (int i = 0; i < 8; i++)
#pragma unroll
                for (int j = 0; j < 8; j++) acc[i][j] += a[i] * b[j];
        }
        __syncthreads();
    }

#pragma unroll
    for (int i = 0; i < 8; i++) {
        int m = m0 + ty * 8 + i;
#pragma unroll
        for (int j = 0; j < 8; j++) {
            int n = n0 + tx * 8 + j;
            if (n < N) {
                float vv = acc[i][j];
                if (OP == 2 || OP == 3) vv += bias[n];
                if (OP == 2) vv = 0.5f * vv * (1.0f + erff(vv * 0.70710678118654752f));
                if (OP == 1 || OP == 3) vv += res[(size_t)m * N + n];
                C[(size_t)m * N + n] = vv;
            }
        }
    }
}

template <int OP, bool TB>
__global__ __launch_bounds__(256) void gemm_kernel(const float* __restrict__ A,
                                                   const float* __restrict__ Bm,
                                                   const float* __restrict__ bias,
                                                   const float* __restrict__ res,
                                                   float* __restrict__ C,
                                                   int M, int N, int K) {
    gemm_body<OP, TB>(A, Bm, bias, res, C, M, N, K, blockIdx.y * 128, blockIdx.x * 128);
}

// Fused QKV: grid.z selects which projection
__global__ __launch_bounds__(256) void qkv_kernel(const float* __restrict__ A,
                                                  const float* __restrict__ Wq,
                                                  const float* __restrict__ Wk,
                                                  const float* __restrict__ Wv,
                                                  float* __restrict__ Qo,
                                                  float* __restrict__ Ko,
                                                  float* __restrict__ Vo) {
    const float* Bm = (blockIdx.z == 0) ? Wq : (blockIdx.z == 1 ? Wk : Wv);
    float* C = (blockIdx.z == 0) ? Qo : (blockIdx.z == 1 ? Ko : Vo);
    gemm_body<0, false>(A, Bm, nullptr, nullptr, C, MROWS, Dm, Dm,
                        blockIdx.y * 128, blockIdx.x * 128);
}

// ---------------------------------------------------------------------------
// Flash attention: grid (S/64, H, B), 256 threads.
// 4 lanes per query row: lane c owns keys c*16..c*16+15 (score phase)
// and output dims c*16..c*16+15 (accumulate phase).
// ---------------------------------------------------------------------------
__global__ __launch_bounds__(256) void attn_kernel(const float* __restrict__ Qg,
                                                   const float* __restrict__ Kg,
                                                   const float* __restrict__ Vg,
                                                   float* __restrict__ Og) {
    __shared__ float Qs[64][64];
    __shared__ float Ks[64][64];
    __shared__ float Vs[64][64];

    int b = blockIdx.z, h = blockIdx.y, qi = blockIdx.x;
    int tid = threadIdx.x;

    // Load Q tile: rows qi*64.., head columns h*64..
    for (int t = tid; t < 1024; t += 256) {
        int r = t >> 4, c4 = t & 15;
        float4 v = *reinterpret_cast<const float4*>(
            Qg + ((size_t)(b * Sq + qi * 64 + r) * Dm) + h * HDm + c4 * 4);
        *reinterpret_cast<float4*>(&Qs[r][c4 * 4]) = v;
    }

    int q = tid >> 2, c = tid & 3;
    float m_i = -INFINITY;
    float l_i = 0.f;
    float o[16];
#pragma unroll
    for (int d = 0; d < 16; d++) o[d] = 0.f;
    const float scale = 0.125f;  // 1/sqrt(64)
    int qg = qi * 64 + q;

    for (int j = 0; j <= qi; j++) {
        __syncthreads();
        for (int t = tid; t < 1024; t += 256) {
            int r = t >> 4, c4 = t & 15;
            size_t base = ((size_t)(b * Sq + j * 64 + r) * Dm) + h * HDm + c4 * 4;
            *reinterpret_cast<float4*>(&Ks[r][c4 * 4]) =
                *reinterpret_cast<const float4*>(Kg + base);
            *reinterpret_cast<float4*>(&Vs[r][c4 * 4]) =
                *reinterpret_cast<const float4*>(Vg + base);
        }
        __syncthreads();

        float s[16];
#pragma unroll
        for (int kk = 0; kk < 16; kk++) s[kk] = 0.f;
#pragma unroll 4
        for (int kd4 = 0; kd4 < 16; kd4++) {
            float4 qv = *reinterpret_cast<const float4*>(&Qs[q][kd4 * 4]);
#pragma unroll
            for (int kk = 0; kk < 16; kk++) {
                float4 kv = *reinterpret_cast<const float4*>(&Ks[c * 16 + kk][kd4 * 4]);
                s[kk] += qv.x * kv.x + qv.y * kv.y + qv.z * kv.z + qv.w * kv.w;
            }
        }
        // scale + causal mask
#pragma unroll
        for (int kk = 0; kk < 16; kk++) {
            int kg = j * 64 + c * 16 + kk;
            s[kk] = (kg <= qg) ? s[kk] * scale : -INFINITY;
        }
        // row max across 16 local + 4-lane group
        float mloc = s[0];
#pragma unroll
        for (int kk = 1; kk < 16; kk++) mloc = fmaxf(mloc, s[kk]);
        mloc = fmaxf(mloc, __shfl_xor_sync(0xffffffffu, mloc, 1, 4));
        mloc = fmaxf(mloc, __shfl_xor_sync(0xffffffffu, mloc, 2, 4));
        float mnew = fmaxf(m_i, mloc);
        float alpha = expf(m_i - mnew);

        float p[16];
        float lloc = 0.f;
#pragma unroll
        for (int kk = 0; kk < 16; kk++) {
            p[kk] = expf(s[kk] - mnew);
            lloc += p[kk];
        }
        lloc += __shfl_xor_sync(0xffffffffu, lloc, 1, 4);
        lloc += __shfl_xor_sync(0xffffffffu, lloc, 2, 4);
        l_i = l_i * alpha + lloc;
        m_i = mnew;
#pragma unroll
        for (int d = 0; d < 16; d++) o[d] *= alpha;

        // o += P @ V   (p broadcast within 4-lane group)
#pragma unroll
        for (int src = 0; src < 4; src++) {
#pragma unroll
            for (int kk = 0; kk < 16; kk++) {
                float pv = __shfl_sync(0xffffffffu, p[kk], src, 4);
                int key = src * 16 + kk;
#pragma unroll
                for (int d4 = 0; d4 < 4; d4++) {
                    float4 vv = *reinterpret_cast<const float4*>(&Vs[key][c * 16 + d4 * 4]);
                    o[d4 * 4 + 0] += pv * vv.x;
                    o[d4 * 4 + 1] += pv * vv.y;
                    o[d4 * 4 + 2] += pv * vv.z;
                    o[d4 * 4 + 3] += pv * vv.w;
                }
            }
        }
    }

    float inv = 1.0f / l_i;
    size_t obase = ((size_t)(b * Sq + qi * 64 + q) * Dm) + h * HDm + c * 16;
#pragma unroll
    for (int d4 = 0; d4 < 4; d4++) {
        float4 ov;
        ov.x = o[d4 * 4 + 0] * inv;
        ov.y = o[d4 * 4 + 1] * inv;
        ov.z = o[d4 * 4 + 2] * inv;
        ov.w = o[d4 * 4 + 3] * inv;
        *reinterpret_cast<float4*>(Og + obase + d4 * 4) = ov;
    }
}

// ---------------------------------------------------------------------------
// Host launch
// ---------------------------------------------------------------------------
extern "C" void kernel_launch(void* const* d_in, const int* in_sizes, int n_in,
                              void* d_out, int out_size) {
    const int*   tokens  = (const int*)d_in[0];
    const float* tok_emb = (const float*)d_in[1];
    const float* pos_emb = (const float*)d_in[2];
    const float* ln1_g   = (const float*)d_in[3];
    const float* ln1_b   = (const float*)d_in[4];
    const float* wq      = (const float*)d_in[5];
    const float* wk      = (const float*)d_in[6];
    const float* wv      = (const float*)d_in[7];
    const float* wo      = (const float*)d_in[8];
    const float* ln2_g   = (const float*)d_in[9];
    const float* ln2_b   = (const float*)d_in[10];
    const float* w1      = (const float*)d_in[11];
    const float* b1      = (const float*)d_in[12];
    const float* w2      = (const float*)d_in[13];
    const float* b2      = (const float*)d_in[14];
    const float* lnf_g   = (const float*)d_in[15];
    const float* lnf_b   = (const float*)d_in[16];
    float* out = (float*)d_out;

    float *px, *ph, *pq, *pk, *pv, *pa, *pf;
    cudaGetSymbolAddress((void**)&px, g_x);
    cudaGetSymbolAddress((void**)&ph, g_h);
    cudaGetSymbolAddress((void**)&pq, g_q);
    cudaGetSymbolAddress((void**)&pk, g_k);
    cudaGetSymbolAddress((void**)&pv, g_v);
    cudaGetSymbolAddress((void**)&pa, g_att);
    cudaGetSymbolAddress((void**)&pf, g_ff);

    // Embedding
    embed_kernel<<<MROWS * Dm / 4 / 256, 256>>>(tokens, tok_emb, pos_emb);

    dim3 gD(Dm / 128, MROWS / 128);        // (8,16)  D x D
    dim3 gQKV(Dm / 128, MROWS / 128, 3);   // fused q,k,v
    dim3 gFF(FFd / 128, MROWS / 128);      // (32,16) D x 4D
    dim3 gAttn(Sq / 64, Hh, Bz);           // (16,16,2)

    for (int l = 0; l < Ll; l++) {
        const float* lWq = wq + (size_t)l * Dm * Dm;
        const float* lWk = wk + (size_t)l * Dm * Dm;
        const float* lWv = wv + (size_t)l * Dm * Dm;
        const float* lWo = wo + (size_t)l * Dm * Dm;
        const float* lW1 = w1 + (size_t)l * Dm * FFd;
        const float* lB1 = b1 + (size_t)l * FFd;
        const float* lW2 = w2 + (size_t)l * FFd * Dm;
        const float* lB2 = b2 + (size_t)l * Dm;

        // ln1
        ln_kernel<<<MROWS, 256>>>(px, ln1_g + (size_t)l * Dm, ln1_b + (size_t)l * Dm, ph);
        // q,k,v projections (fused launch)
        qkv_kernel<<<gQKV, 256>>>(ph, lWq, lWk, lWv, pq, pk, pv);
        // attention
        attn_kernel<<<gAttn, 256>>>(pq, pk, pv, pa);
        // x = x + att @ Wo
        gemm_kernel<1, false><<<gD, 256>>>(pa, lWo, nullptr, px, px, MROWS, Dm, Dm);
        // ln2
        ln_kernel<<<MROWS, 256>>>(px, ln2_g + (size_t)l * Dm, ln2_b + (size_t)l * Dm, ph);
        // ff = gelu(h @ W1 + b1)
        gemm_kernel<2, false><<<gFF, 256>>>(ph, lW1, lB1, nullptr, pf, MROWS, FFd, Dm);
        // x = x + ff @ W2 + b2
        gemm_kernel<3, false><<<gD, 256>>>(pf, lW2, lB2, px, px, MROWS, Dm, FFd);
    }

    // final LN + tied logits head: out = lnf(x) @ tok_emb^T
    ln_kernel<<<MROWS, 256>>>(px, lnf_g, lnf_b, ph);
    dim3 gLog((Vv + 127) / 128, MROWS / 128);  // (393,16)
    gemm_kernel<0, true><<<gLog, 256>>>(ph, tok_emb, nullptr, nullptr, out,
                                        MROWS, Vv, Dm);
}

// round 2
// speedup vs baseline: 1.9137x; 1.9137x over previous
#include <cuda_runtime.h>
#include <math.h>
#include <stdint.h>

// Problem constants
#define Bz 2
#define Sq 1024
#define Dm 1024
#define Hh 16
#define Ll 6
#define Vv 50257
#define HDm 64
#define MROWS (Bz * Sq)   // 2048
#define FFd (4 * Dm)      // 4096

// Scratch
__device__ float g_x[MROWS * Dm];
__device__ float g_h[MROWS * Dm];
__device__ float g_q[MROWS * Dm];
__device__ float g_k[MROWS * Dm];
__device__ float g_v[MROWS * Dm];
__device__ float g_att[MROWS * Dm];
__device__ float g_ff[MROWS * FFd];

// ---------------------------------------------------------------------------
// Helpers
// ---------------------------------------------------------------------------
__device__ __forceinline__ uint32_t f2tf(float x) {
    uint32_t r;
    asm("cvt.rna.tf32.f32 %0, %1;" : "=r"(r) : "f"(x));
    return r;
}

__device__ __forceinline__ void cpasync16(void* smem_dst, const void* gsrc) {
    uint32_t d = (uint32_t)__cvta_generic_to_shared(smem_dst);
    asm volatile("cp.async.ca.shared.global [%0], [%1], 16;" :: "r"(d), "l"(gsrc));
}
#define CP_COMMIT() asm volatile("cp.async.commit_group;")
#define CP_WAIT1()  asm volatile("cp.async.wait_group 1;")
#define CP_WAIT0()  asm volatile("cp.async.wait_group 0;")

__device__ __forceinline__ void mma_tf32(float* c, const uint32_t* a, const uint32_t* b) {
    asm volatile(
        "mma.sync.aligned.m16n8k8.row.col.f32.tf32.tf32.f32 "
        "{%0,%1,%2,%3}, {%4,%5,%6,%7}, {%8,%9}, {%0,%1,%2,%3};"
        : "+f"(c[0]), "+f"(c[1]), "+f"(c[2]), "+f"(c[3])
        : "r"(a[0]), "r"(a[1]), "r"(a[2]), "r"(a[3]), "r"(b[0]), "r"(b[1]));
}

// ---------------------------------------------------------------------------
// Embedding
// ---------------------------------------------------------------------------
__global__ void embed_kernel(const int* __restrict__ tokens,
                             const float* __restrict__ tok_emb,
                             const float* __restrict__ pos_emb) {
    int idx = blockIdx.x * blockDim.x + threadIdx.x;
    if (idx >= MROWS * Dm / 4) return;
    int row = idx / (Dm / 4);
    int c4  = idx % (Dm / 4);
    int s   = row % Sq;
    int tok = tokens[row];
    float4 te = reinterpret_cast<const float4*>(tok_emb + (size_t)tok * Dm)[c4];
    float4 pe = reinterpret_cast<const float4*>(pos_emb + (size_t)s * Dm)[c4];
    te.x += pe.x; te.y += pe.y; te.z += pe.z; te.w += pe.w;
    reinterpret_cast<float4*>(g_x)[idx] = te;
}

// ---------------------------------------------------------------------------
// LayerNorm
// ---------------------------------------------------------------------------
__global__ __launch_bounds__(256) void ln_kernel(const float* __restrict__ x,
                                                 const float* __restrict__ gw,
                                                 const float* __restrict__ bw,
                                                 float* __restrict__ out) {
    int row = blockIdx.x;
    int tid = threadIdx.x;
    const float* xr = x + (size_t)row * Dm;

    float v[4];
    float s = 0.f, s2 = 0.f;
#pragma unroll
    for (int i = 0; i < 4; i++) {
        v[i] = xr[tid + i * 256];
        s += v[i];
        s2 += v[i] * v[i];
    }
#pragma unroll
    for (int o = 16; o > 0; o >>= 1) {
        s  += __shfl_xor_sync(0xffffffffu, s,  o);
        s2 += __shfl_xor_sync(0xffffffffu, s2, o);
    }
    __shared__ float ws[8], ws2[8];
    int w = tid >> 5, l = tid & 31;
    if (l == 0) { ws[w] = s; ws2[w] = s2; }
    __syncthreads();
    s = 0.f; s2 = 0.f;
#pragma unroll
    for (int i = 0; i < 8; i++) { s += ws[i]; s2 += ws2[i]; }
    float mean = s * (1.0f / Dm);
    float var  = s2 * (1.0f / Dm) - mean * mean;
    float rstd = rsqrtf(var + 1e-5f);

    float* orow = out + (size_t)row * Dm;
#pragma unroll
    for (int i = 0; i < 4; i++) {
        int col = tid + i * 256;
        orow[col] = (v[i] - mean) * rstd * gw[col] + bw[col];
    }
}

// ---------------------------------------------------------------------------
// TF32 tensor-core GEMM: C[M,N] = A[M,K] @ B ; B is [K,N] (or [N,K] if TB)
// Block 128x128, BK=16, 256 threads (8 warps, 2x4), warp tile 64x32.
// Epilogue OP: 0 none, 1 +res, 2 gelu(acc+bias), 3 res+acc+bias
// smem: A as [128][20] (stride-20 pad), B as [16][132] (non-TB) or [128][20] (TB)
// ---------------------------------------------------------------------------
#define ASTRIDE 20
#define BSTRIDE 132

template <int OP, bool TB>
__device__ __forceinline__ void gemm_mma_body(const float* __restrict__ A,
                                              const float* __restrict__ Bm,
                                              const float* __restrict__ bias,
                                              const float* __restrict__ res,
                                              float* __restrict__ C,
                                              int M, int N, int K,
                                              int m0, int n0) {
    __shared__ float sA[2][128 * ASTRIDE];
    __shared__ float sB[2][2560];   // max(16*132, 128*20)

    int tid = threadIdx.x;
    int warp = tid >> 5;
    int lane = tid & 31;
    int g  = lane >> 2;   // group 0..7
    int tg = lane & 3;    // 0..3
    int wm = warp & 1;    // 0..1 -> 64 M rows each
    int wn = warp >> 1;   // 0..3 -> 32 N cols each

    float acc[4][4][4];
#pragma unroll
    for (int mt = 0; mt < 4; mt++)
#pragma unroll
        for (int nt = 0; nt < 4; nt++)
#pragma unroll
            for (int i = 0; i < 4; i++) acc[mt][nt][i] = 0.f;

    // ---- load indices ----
    // A tile: 128 rows x 16 k. 512 float4 slots: id -> m=id/4, kc=id%4
    int a_m  = tid >> 1;            // with 2 passes: slots tid + p*256
    // B (non-TB): 16 rows x 128 cols: 512 slots: id -> k=id/32, n4=id%32
    // B (TB): 128 rows x 4 chunks: id -> n=id/4, kc=id%4

    int KT = K / 16;

    // prologue: stage 0
    {
        int k0 = 0;
#pragma unroll
        for (int p = 0; p < 2; p++) {
            int id = tid + p * 256;
            int m = id >> 2, kc = id & 3;
            cpasync16(&sA[0][m * ASTRIDE + kc * 4],
                      A + (size_t)(m0 + m) * K + k0 + kc * 4);
        }
        if (!TB) {
#pragma unroll
            for (int p = 0; p < 2; p++) {
                int id = tid + p * 256;
                int k = id >> 5, n4 = id & 31;
                cpasync16(&sB[0][k * BSTRIDE + n4 * 4],
                          Bm + (size_t)(k0 + k) * N + n0 + n4 * 4);
            }
        } else {
#pragma unroll
            for (int p = 0; p < 2; p++) {
                int id = tid + p * 256;
                int n = id >> 2, kc = id & 3;
                int nn = n0 + n; if (nn > N - 1) nn = N - 1;
                cpasync16(&sB[0][n * ASTRIDE + kc * 4],
                          Bm + (size_t)nn * K + k0 + kc * 4);
            }
        }
        CP_COMMIT();
    }

    int stage = 0;
    for (int kt = 0; kt < KT; kt++) {
        if (kt + 1 < KT) {
            int k0 = (kt + 1) * 16;
            int ns = stage ^ 1;
#pragma unroll
            for (int p = 0; p < 2; p++) {
                int id = tid + p * 256;
                int m = id >> 2, kc = id & 3;
                cpasync16(&sA[ns][m * ASTRIDE + kc * 4],
                          A + (size_t)(m0 + m) * K + k0 + kc * 4);
            }
            if (!TB) {
#pragma unroll
                for (int p = 0; p < 2; p++) {
                    int id = tid + p * 256;
                    int k = id >> 5, n4 = id & 31;
                    cpasync16(&sB[ns][k * BSTRIDE + n4 * 4],
                              Bm + (size_t)(k0 + k) * N + n0 + n4 * 4);
                }
            } else {
#pragma unroll
                for (int p = 0; p < 2; p++) {
                    int id = tid + p * 256;
                    int n = id >> 2, kc = id & 3;
                    int nn = n0 + n; if (nn > N - 1) nn = N - 1;
                    cpasync16(&sB[ns][n * ASTRIDE + kc * 4],
                              Bm + (size_t)nn * K + k0 + kc * 4);
                }
            }
            CP_COMMIT();
            CP_WAIT1();
        } else {
            CP_WAIT0();
        }
        __syncthreads();

        const float* As = sA[stage];
        const float* Bs = sB[stage];

#pragma unroll
        for (int kk = 0; kk < 2; kk++) {
            int kb = kk * 8;
            uint32_t afr[4][4];
#pragma unroll
            for (int mt = 0; mt < 4; mt++) {
                int rowb = wm * 64 + mt * 16;
                afr[mt][0] = f2tf(As[(rowb + g) * ASTRIDE + kb + tg]);
                afr[mt][1] = f2tf(As[(rowb + g + 8) * ASTRIDE + kb + tg]);
                afr[mt][2] = f2tf(As[(rowb + g) * ASTRIDE + kb + tg + 4]);
                afr[mt][3] = f2tf(As[(rowb + g + 8) * ASTRIDE + kb + tg + 4]);
            }
            uint32_t bfr[4][2];
#pragma unroll
            for (int nt = 0; nt < 4; nt++) {
                int col = wn * 32 + nt * 8 + g;
                if (!TB) {
                    bfr[nt][0] = f2tf(Bs[(kb + tg) * BSTRIDE + col]);
                    bfr[nt][1] = f2tf(Bs[(kb + tg + 4) * BSTRIDE + col]);
                } else {
                    bfr[nt][0] = f2tf(Bs[col * ASTRIDE + kb + tg]);
                    bfr[nt][1] = f2tf(Bs[col * ASTRIDE + kb + tg + 4]);
                }
            }
#pragma unroll
            for (int mt = 0; mt < 4; mt++)
#pragma unroll
                for (int nt = 0; nt < 4; nt++)
                    mma_tf32(acc[mt][nt], afr[mt], bfr[nt]);
        }
        __syncthreads();
        stage ^= 1;
    }

    // ---- epilogue ----
#pragma unroll
    for (int mt = 0; mt < 4; mt++) {
#pragma unroll
        for (int half = 0; half < 2; half++) {
            int m = m0 + wm * 64 + mt * 16 + g + half * 8;
#pragma unroll
            for (int nt = 0; nt < 4; nt++) {
                int col = n0 + wn * 32 + nt * 8 + tg * 2;
                float v0 = acc[mt][nt][half * 2 + 0];
                float v1 = acc[mt][nt][half * 2 + 1];
                if (OP == 2 || OP == 3) {
                    // guard bias index when TB tail (TB is OP0 in practice)
                    v0 += bias[col];
                    v1 += bias[col + 1];
                }
                if (OP == 2) {
                    v0 = 0.5f * v0 * (1.0f + erff(v0 * 0.70710678118654752f));
                    v1 = 0.5f * v1 * (1.0f + erff(v1 * 0.70710678118654752f));
                }
                if (OP == 1 || OP == 3) {
                    float2 r = *reinterpret_cast<const float2*>(res + (size_t)m * N + col);
                    v0 += r.x; v1 += r.y;
                }
                if (TB) {
                    if (col < N)     C[(size_t)m * N + col]     = v0;
                    if (col + 1 < N) C[(size_t)m * N + col + 1] = v1;
                } else {
                    float2 o; o.x = v0; o.y = v1;
                    *reinterpret_cast<float2*>(C + (size_t)m * N + col) = o;
                }
            }
        }
    }
}

template <int OP, bool TB>
__global__ __launch_bounds__(256) void gemm_mma_kernel(const float* __restrict__ A,
                                                       const float* __restrict__ Bm,
                                                       const float* __restrict__ bias,
                                                       const float* __restrict__ res,
                                                       float* __restrict__ C,
                                                       int M, int N, int K) {
    gemm_mma_body<OP, TB>(A, Bm, bias, res, C, M, N, K,
                          blockIdx.y * 128, blockIdx.x * 128);
}

__global__ __launch_bounds__(256) void qkv_mma_kernel(const float* __restrict__ A,
                                                      const float* __restrict__ Wq,
                                                      const float* __restrict__ Wk,
                                                      const float* __restrict__ Wv,
                                                      float* __restrict__ Qo,
                                                      float* __restrict__ Ko,
                                                      float* __restrict__ Vo) {
    const float* Bm = (blockIdx.z == 0) ? Wq : (blockIdx.z == 1 ? Wk : Wv);
    float* C = (blockIdx.z == 0) ? Qo : (blockIdx.z == 1 ? Ko : Vo);
    gemm_mma_body<0, false>(A, Bm, nullptr, nullptr, C, MROWS, Dm, Dm,
                            blockIdx.y * 128, blockIdx.x * 128);
}

// ---------------------------------------------------------------------------
// Flash attention (fp32 SIMT, unchanged)
// ---------------------------------------------------------------------------
__global__ __launch_bounds__(256) void attn_kernel(const float* __restrict__ Qg,
                                                   const float* __restrict__ Kg,
                                                   const float* __restrict__ Vg,
                                                   float* __restrict__ Og) {
    __shared__ float Qs[64][64];
    __shared__ float Ks[64][64];
    __shared__ float Vs[64][64];

    int b = blockIdx.z, h = blockIdx.y, qi = blockIdx.x;
    int tid = threadIdx.x;

    for (int t = tid; t < 1024; t += 256) {
        int r = t >> 4, c4 = t & 15;
        float4 v = *reinterpret_cast<const float4*>(
            Qg + ((size_t)(b * Sq + qi * 64 + r) * Dm) + h * HDm + c4 * 4);
        *reinterpret_cast<float4*>(&Qs[r][c4 * 4]) = v;
    }

    int q = tid >> 2, c = tid & 3;
    float m_i = -INFINITY;
    float l_i = 0.f;
    float o[16];
#pragma unroll
    for (int d = 0; d < 16; d++) o[d] = 0.f;
    const float scale = 0.125f;
    int qg = qi * 64 + q;

    for (int j = 0; j <= qi; j++) {
        __syncthreads();
        for (int t = tid; t < 1024; t += 256) {
            int r = t >> 4, c4 = t & 15;
            size_t base = ((size_t)(b * Sq + j * 64 + r) * Dm) + h * HDm + c4 * 4;
            *reinterpret_cast<float4*>(&Ks[r][c4 * 4]) =
                *reinterpret_cast<const float4*>(Kg + base);
            *reinterpret_cast<float4*>(&Vs[r][c4 * 4]) =
                *reinterpret_cast<const float4*>(Vg + base);
        }
        __syncthreads();

        float s[16];
#pragma unroll
        for (int kk = 0; kk < 16; kk++) s[kk] = 0.f;
#pragma unroll 4
        for (int kd4 = 0; kd4 < 16; kd4++) {
            float4 qv = *reinterpret_cast<const float4*>(&Qs[q][kd4 * 4]);
#pragma unroll
            for (int kk = 0; kk < 16; kk++) {
                float4 kv = *reinterpret_cast<const float4*>(&Ks[c * 16 + kk][kd4 * 4]);
                s[kk] += qv.x * kv.x + qv.y * kv.y + qv.z * kv.z + qv.w * kv.w;
            }
        }
#pragma unroll
        for (int kk = 0; kk < 16; kk++) {
            int kg = j * 64 + c * 16 + kk;
            s[kk] = (kg <= qg) ? s[kk] * scale : -INFINITY;
        }
        float mloc = s[0];
#pragma unroll
        for (int kk = 1; kk < 16; kk++) mloc = fmaxf(mloc, s[kk]);
        mloc = fmaxf(mloc, __shfl_xor_sync(0xffffffffu, mloc, 1, 4));
        mloc = fmaxf(mloc, __shfl_xor_sync(0xffffffffu, mloc, 2, 4));
        float mnew = fmaxf(m_i, mloc);
        float alpha = expf(m_i - mnew);

        float p[16];
        float lloc = 0.f;
#pragma unroll
        for (int kk = 0; kk < 16; kk++) {
            p[kk] = expf(s[kk] - mnew);
            lloc += p[kk];
        }
        lloc += __shfl_xor_sync(0xffffffffu, lloc, 1, 4);
        lloc += __shfl_xor_sync(0xffffffffu, lloc, 2, 4);
        l_i = l_i * alpha + lloc;
        m_i = mnew;
#pragma unroll
        for (int d = 0; d < 16; d++) o[d] *= alpha;

#pragma unroll
        for (int src = 0; src < 4; src++) {
#pragma unroll
            for (int kk = 0; kk < 16; kk++) {
                float pv = __shfl_sync(0xffffffffu, p[kk], src, 4);
                int key = src * 16 + kk;
#pragma unroll
                for (int d4 = 0; d4 < 4; d4++) {
                    float4 vv = *reinterpret_cast<const float4*>(&Vs[key][c * 16 + d4 * 4]);
                    o[d4 * 4 + 0] += pv * vv.x;
                    o[d4 * 4 + 1] += pv * vv.y;
                    o[d4 * 4 + 2] += pv * vv.z;
                    o[d4 * 4 + 3] += pv * vv.w;
                }
            }
        }
    }

    float inv = 1.0f / l_i;
    size_t obase = ((size_t)(b * Sq + qi * 64 + q) * Dm) + h * HDm + c * 16;
#pragma unroll
    for (int d4 = 0; d4 < 4; d4++) {
        float4 ov;
        ov.x = o[d4 * 4 + 0] * inv;
        ov.y = o[d4 * 4 + 1] * inv;
        ov.z = o[d4 * 4 + 2] * inv;
        ov.w = o[d4 * 4 + 3] * inv;
        *reinterpret_cast<float4*>(Og + obase + d4 * 4) = ov;
    }
}

// ---------------------------------------------------------------------------
// Host launch
// ---------------------------------------------------------------------------
extern "C" void kernel_launch(void* const* d_in, const int* in_sizes, int n_in,
                              void* d_out, int out_size) {
    const int*   tokens  = (const int*)d_in[0];
    const float* tok_emb = (const float*)d_in[1];
    const float* pos_emb = (const float*)d_in[2];
    const float* ln1_g   = (const float*)d_in[3];
    const float* ln1_b   = (const float*)d_in[4];
    const float* wq      = (const float*)d_in[5];
    const float* wk      = (const float*)d_in[6];
    const float* wv      = (const float*)d_in[7];
    const float* wo      = (const float*)d_in[8];
    const float* ln2_g   = (const float*)d_in[9];
    const float* ln2_b   = (const float*)d_in[10];
    const float* w1      = (const float*)d_in[11];
    const float* b1      = (const float*)d_in[12];
    const float* w2      = (const float*)d_in[13];
    const float* b2      = (const float*)d_in[14];
    const float* lnf_g   = (const float*)d_in[15];
    const float* lnf_b   = (const float*)d_in[16];
    float* out = (float*)d_out;

    float *px, *ph, *pq, *pk, *pv, *pa, *pf;
    cudaGetSymbolAddress((void**)&px, g_x);
    cudaGetSymbolAddress((void**)&ph, g_h);
    cudaGetSymbolAddress((void**)&pq, g_q);
    cudaGetSymbolAddress((void**)&pk, g_k);
    cudaGetSymbolAddress((void**)&pv, g_v);
    cudaGetSymbolAddress((void**)&pa, g_att);
    cudaGetSymbolAddress((void**)&pf, g_ff);

    embed_kernel<<<MROWS * Dm / 4 / 256, 256>>>(tokens, tok_emb, pos_emb);

    dim3 gD(Dm / 128, MROWS / 128);        // (8,16)
    dim3 gQKV(Dm / 128, MROWS / 128, 3);
    dim3 gFF(FFd / 128, MROWS / 128);      // (32,16)
    dim3 gAttn(Sq / 64, Hh, Bz);

    for (int l = 0; l < Ll; l++) {
        const float* lWq = wq + (size_t)l * Dm * Dm;
        const float* lWk = wk + (size_t)l * Dm * Dm;
        const float* lWv = wv + (size_t)l * Dm * Dm;
        const float* lWo = wo + (size_t)l * Dm * Dm;
        const float* lW1 = w1 + (size_t)l * Dm * FFd;
        const float* lB1 = b1 + (size_t)l * FFd;
        const float* lW2 = w2 + (size_t)l * FFd * Dm;
        const float* lB2 = b2 + (size_t)l * Dm;

        ln_kernel<<<MROWS, 256>>>(px, ln1_g + (size_t)l * Dm, ln1_b + (size_t)l * Dm, ph);
        qkv_mma_kernel<<<gQKV, 256>>>(ph, lWq, lWk, lWv, pq, pk, pv);
        attn_kernel<<<gAttn, 256>>>(pq, pk, pv, pa);
        gemm_mma_kernel<1, false><<<gD, 256>>>(pa, lWo, nullptr, px, px, MROWS, Dm, Dm);
        ln_kernel<<<MROWS, 256>>>(px, ln2_g + (size_t)l * Dm, ln2_b + (size_t)l * Dm, ph);
        gemm_mma_kernel<2, false><<<gFF, 256>>>(ph, lW1, lB1, nullptr, pf, MROWS, FFd, Dm);
        gemm_mma_kernel<3, false><<<gD, 256>>>(pf, lW2, lB2, px, px, MROWS, Dm, FFd);
    }

    ln_kernel<<<MROWS, 256>>>(px, lnf_g, lnf_b, ph);
    dim3 gLog((Vv + 127) / 128, MROWS / 128);  // (393,16)
    gemm_mma_kernel<0, true><<<gLog, 256>>>(ph, tok_emb, nullptr, nullptr, out,
                                            MROWS, Vv, Dm);
}